// round 8
// baseline (speedup 1.0000x reference)
#include <cuda_runtime.h>
#include <cuda_bf16.h>
#include <stdint.h>

// FuzzyPooling: 2x2 stride-2 pooling with fuzzy membership selection.
// x: (32,64,128,128) fp32 -> out: (32,64,64,64) fp32
//
// mu1 = tri(v,1.5,1.5); mu2 = tri(v,3.0,1.5); mu3 == mu2 (identical
// constants), argmax takes first max -> sel = (s1 >= s2) ? mu1 : mu2.
// Memberships appear only in scale-invariant positions (compare, ratio,
// zero-test) -> unnormalized (x1.5):
//   u1 = max(1.5 - |v - 1.5|, 0)     u2 = max(1.5 - |v - 3.0|, 0)
// The abs form lowers to FADD, FADD(-|w|), FMNMX -> 2 fma-pipe + 1 alu-pipe
// ops vs 3 alu-pipe FMNMX in the min/max form, rebalancing off the
// busier alu pipe.
//
// R7 = R6 (best: 25.4us) + abs-form memberships.

#define N_OUT  (32 * 64 * 64 * 64)   // 8,388,608

__device__ __forceinline__ void memb(float v, float& u1, float& u2) {
    float w1 = v - 1.5f;
    float w2 = v - 3.0f;
    u1 = fmaxf(1.5f - fabsf(w1), 0.0f);
    u2 = fmaxf(1.5f - fabsf(w2), 0.0f);
}

__device__ __forceinline__ float fuzzy_patch(float a, float b, float c, float d) {
    float m1a, m2a, m1b, m2b, m1c, m2c, m1d, m2d;
    memb(a, m1a, m2a);
    memb(b, m1b, m2b);
    memb(c, m1c, m2c);
    memb(d, m1d, m2d);

    float s1 = (m1a + m1b) + (m1c + m1d);
    float s2 = (m2a + m2b) + (m2c + m2d);
    bool pick1 = (s1 >= s2);

    float ma = pick1 ? m1a : m2a;
    float mb = pick1 ? m1b : m2b;
    float mc = pick1 ? m1c : m2c;
    float md = pick1 ? m1d : m2d;

    float ta = ma * a, tb = mb * b, tc = mc * c, td = md * d;
    float den = (ta + tb) + (tc + td);
    float num = fmaf(ta, a, fmaf(tb, b, fmaf(tc, c, td * d)));

    float r = __fdividef(num, den);      // rcp + mul; den==0 handled below
    return (den == 0.0f) ? 0.0f : r;
}

__global__ __launch_bounds__(256)
void fuzzy_pool_kernel(const float* __restrict__ x, float* __restrict__ out) {
    unsigned tid = blockIdx.x * blockDim.x + threadIdx.x;   // < 2,097,152

    // collapsed offsets: out = 4*tid, in = 16*tid - 8*(tid&15)
    unsigned in_off  = 16u * tid - 8u * (tid & 15u);  // float index of row0
    unsigned out_off = 4u * tid;                      // float index

    const float4* r0 = reinterpret_cast<const float4*>(x + in_off);
    const float4* r1 = r0 + 32;                       // next input row

    // 4 independent streaming loads in flight before any compute
    float4 a0 = __ldcs(r0);
    float4 a1 = __ldcs(r0 + 1);
    float4 b0 = __ldcs(r1);
    float4 b1 = __ldcs(r1 + 1);

    float4 o;
    o.x = fuzzy_patch(a0.x, a0.y, b0.x, b0.y);
    o.y = fuzzy_patch(a0.z, a0.w, b0.z, b0.w);
    o.z = fuzzy_patch(a1.x, a1.y, b1.x, b1.y);
    o.w = fuzzy_patch(a1.z, a1.w, b1.z, b1.w);

    __stcs(reinterpret_cast<float4*>(out + out_off), o);
}

extern "C" void kernel_launch(void* const* d_in, const int* in_sizes, int n_in,
                              void* d_out, int out_size) {
    const float* x = (const float*)d_in[0];
    float* out = (float*)d_out;
    int threads = 256;
    int blocks = (N_OUT / 4) / threads;   // 8192 exactly
    fuzzy_pool_kernel<<<blocks, threads>>>(x, out);
}

// round 9
// speedup vs baseline: 1.0661x; 1.0661x over previous
#include <cuda_runtime.h>
#include <cuda_bf16.h>
#include <stdint.h>

// FuzzyPooling: 2x2 stride-2 pooling with fuzzy membership selection.
// x: (32,64,128,128) fp32 -> out: (32,64,64,64) fp32
//
// mu1 = tri(v,1.5,1.5); mu2 = tri(v,3.0,1.5); mu3 == mu2 (identical
// constants), argmax takes first max -> sel = (s1 >= s2) ? mu1 : mu2.
// Unnormalized memberships (scale-invariant use): u_c(v) = max(1.5-|v-c|,0).
//
// R8 = R7 (best kernel: 24.5us, math-issue-bound: fma+alu ~= issue) +
//  (a) packed f32x2 adds for the w = v - center subtractions. Patch pairs
//      (a,b)/(c,d) are natively aligned register pairs from the float4
//      loads, so pack/unpack movs should vanish in SASS. 32 FADD -> 16.
//  (b) den==0 guard -> num * rcp(max(den,1e-35)). Valid because v>=0,
//      m>=0 => den==0 implies every m*v==0 implies num==0 -> result 0.
//      Removes FSETP+FSEL per patch, adds one FMNMX.

#define N_OUT  (32 * 64 * 64 * 64)   // 8,388,608

typedef unsigned long long ull;

__device__ __forceinline__ ull f2_pack(float lo, float hi) {
    ull r; asm("mov.b64 %0, {%1, %2};" : "=l"(r) : "f"(lo), "f"(hi)); return r;
}
__device__ __forceinline__ float2 f2_unpack(ull p) {
    float2 v; asm("mov.b64 {%0, %1}, %2;" : "=f"(v.x), "=f"(v.y) : "l"(p)); return v;
}
__device__ __forceinline__ ull f2_add(ull a, ull b) {
    ull r; asm("add.rn.f32x2 %0, %1, %2;" : "=l"(r) : "l"(a), "l"(b)); return r;
}

// one triangular membership (unnormalized): max(1.5 - |w|, 0)
__device__ __forceinline__ float tri_w(float w) {
    return fmaxf(1.5f - fabsf(w), 0.0f);
}

__device__ __forceinline__ float fuzzy_patch(float2 top, float2 bot,
                                             ull C15, ull C30) {
    ull tp = f2_pack(top.x, top.y);
    ull bp = f2_pack(bot.x, bot.y);

    // packed w = v - center (2 lanes per instruction)
    float2 w1t = f2_unpack(f2_add(tp, C15));
    float2 w2t = f2_unpack(f2_add(tp, C30));
    float2 w1b = f2_unpack(f2_add(bp, C15));
    float2 w2b = f2_unpack(f2_add(bp, C30));

    float m1a = tri_w(w1t.x), m1b = tri_w(w1t.y), m1c = tri_w(w1b.x), m1d = tri_w(w1b.y);
    float m2a = tri_w(w2t.x), m2b = tri_w(w2t.y), m2c = tri_w(w2b.x), m2d = tri_w(w2b.y);

    float s1 = (m1a + m1b) + (m1c + m1d);
    float s2 = (m2a + m2b) + (m2c + m2d);
    bool pick1 = (s1 >= s2);

    float ma = pick1 ? m1a : m2a;
    float mb = pick1 ? m1b : m2b;
    float mc = pick1 ? m1c : m2c;
    float md = pick1 ? m1d : m2d;

    float a = top.x, b = top.y, c = bot.x, d = bot.y;
    float ta = ma * a, tb = mb * b, tc = mc * c, td = md * d;
    float den = (ta + tb) + (tc + td);
    float num = fmaf(ta, a, fmaf(tb, b, fmaf(tc, c, td * d)));

    // den==0 => num==0 => 0 * rcp(1e-35) == 0 exactly; no select needed
    return __fdividef(num, fmaxf(den, 1e-35f));
}

__global__ __launch_bounds__(256)
void fuzzy_pool_kernel(const float* __restrict__ x, float* __restrict__ out) {
    unsigned tid = blockIdx.x * blockDim.x + threadIdx.x;   // < 2,097,152

    // collapsed offsets: out = 4*tid, in = 16*tid - 8*(tid&15)
    unsigned in_off  = 16u * tid - 8u * (tid & 15u);
    unsigned out_off = 4u * tid;

    const float4* r0 = reinterpret_cast<const float4*>(x + in_off);
    const float4* r1 = r0 + 32;                       // next input row

    float4 a0 = __ldcs(r0);
    float4 a1 = __ldcs(r0 + 1);
    float4 b0 = __ldcs(r1);
    float4 b1 = __ldcs(r1 + 1);

    const ull C15 = f2_pack(-1.5f, -1.5f);
    const ull C30 = f2_pack(-3.0f, -3.0f);

    float4 o;
    o.x = fuzzy_patch(make_float2(a0.x, a0.y), make_float2(b0.x, b0.y), C15, C30);
    o.y = fuzzy_patch(make_float2(a0.z, a0.w), make_float2(b0.z, b0.w), C15, C30);
    o.z = fuzzy_patch(make_float2(a1.x, a1.y), make_float2(b1.x, b1.y), C15, C30);
    o.w = fuzzy_patch(make_float2(a1.z, a1.w), make_float2(b1.z, b1.w), C15, C30);

    __stcs(reinterpret_cast<float4*>(out + out_off), o);
}

extern "C" void kernel_launch(void* const* d_in, const int* in_sizes, int n_in,
                              void* d_out, int out_size) {
    const float* x = (const float*)d_in[0];
    float* out = (float*)d_out;
    int threads = 256;
    int blocks = (N_OUT / 4) / threads;   // 8192 exactly
    fuzzy_pool_kernel<<<blocks, threads>>>(x, out);
}